// round 15
// baseline (speedup 1.0000x reference)
#include <cuda_runtime.h>
#include <cstdint>

// ---------------------------------------------------------------------------
// Compile-time schedule: fold the 24 CNOT permutations (GF(2)-linear) into
// the gate shuffle masks (see R9).
// ---------------------------------------------------------------------------
struct PermSched { int sh[24]; int sel[24]; int fin[16]; };

constexpr PermSched make_sched() {
    PermSched P{};
    int F[4] = {1, 2, 4, 8};
    int G[4] = {1, 2, 4, 8};
    int g = 0;
    for (int l = 0; l < 6; ++l) {
        for (int w = 0; w < 4; ++w) {
            int b = 3 - w;
            P.sh[g] = G[b];
            int S = 0;
            for (int j = 0; j < 4; ++j) S |= ((F[j] >> b) & 1) << j;
            P.sel[g] = S;
            ++g;
        }
        int r = l % 3 + 1;
        for (int w = 0; w < 4; ++w) {
            int bc = 3 - w, bt = 3 - ((w + r) & 3);
            for (int b2 = 0; b2 < 4; ++b2)
                if ((F[b2] >> bc) & 1) F[b2] ^= (1 << bt);
            G[bc] ^= G[bt];
        }
    }
    for (int k = 0; k < 16; ++k) {
        int t = 0;
        for (int b = 0; b < 4; ++b) if ((k >> b) & 1) t ^= F[b];
        P.fin[k] = t;
    }
    return P;
}
__device__ constexpr PermSched PS = make_sched();

__device__ __forceinline__ float2 cmul(float2 a, float2 b) {
    return make_float2(a.x * b.x - a.y * b.y, a.x * b.y + a.y * b.x);
}

// tf32 truncation split: hi = top 19 bits (valid tf32), lo = exact remainder
__device__ __forceinline__ float tf32_hi(float x) {
    return __uint_as_float(__float_as_uint(x) & 0xFFFFE000u);
}

// m16n8k8 tf32 warp MMA, C += A*B  (fp32 accumulate)
__device__ __forceinline__ void mma_tf32(float* c,
                                         float a0, float a1, float a2, float a3,
                                         float b0, float b1) {
    asm volatile(
        "mma.sync.aligned.m16n8k8.row.col.f32.tf32.tf32.f32 "
        "{%0,%1,%2,%3}, {%4,%5,%6,%7}, {%8,%9}, {%0,%1,%2,%3};"
        : "+f"(c[0]), "+f"(c[1]), "+f"(c[2]), "+f"(c[3])
        : "r"(__float_as_uint(a0)), "r"(__float_as_uint(a1)),
          "r"(__float_as_uint(a2)), "r"(__float_as_uint(a3)),
          "r"(__float_as_uint(b0)), "r"(__float_as_uint(b1)));
}

#define WARPS 8
#define NGROUPS 8192   // 262144 / 32

// ---------------------------------------------------------------------------
// Fused tensor-core kernel, occupancy-3 restructure.
//   Per group, the two 16-row halves (mt) are processed SEQUENTIALLY so live
//   registers stay ~85: build A frags for 2 elements, 24 mma (3-pass tf32),
//   tensor-core Z-sign reduction epilogue (2-pass), store, release.
//   B fragments (tf32 hi/lo of [Re|Im]U) and Z-sign B frags are loop-invariant
//   registers. Prep (folded-perm shuffle propagation of U) unchanged.
// ---------------------------------------------------------------------------
__global__ __launch_bounds__(256, 3)
void qtc_kernel(const float4* __restrict__ x4, const float* __restrict__ wts,
                float4* __restrict__ out4) {
    __shared__ float2 sUc[256];    // sUc[j*16 + k] = U[k][j]
    __shared__ float2 sm[24][4];

    int tid  = threadIdx.x;
    int wid  = tid >> 5;
    int lane = tid & 31;
    int gid  = lane >> 2;   // mma "groupID"
    int tid4 = lane & 3;    // mma "threadID_in_group"

    // ---- gate matrices ----
    if (tid < 24) {
        float ph = wts[tid * 3 + 0];
        float th = wts[tid * 3 + 1];
        float om = wts[tid * 3 + 2];
        float st, ct; __sincosf(0.5f * th, &st, &ct);
        float sa, ca; __sincosf(0.5f * (ph + om), &sa, &ca);
        float sb, cb; __sincosf(0.5f * (ph - om), &sb, &cb);
        sm[tid][0] = make_float2( ca * ct, -sa * ct);
        sm[tid][1] = make_float2(-cb * st, -sb * st);
        sm[tid][2] = make_float2( cb * st, -sb * st);
        sm[tid][3] = make_float2( ca * ct,  sa * ct);
    }
    __syncthreads();

    // ---- U propagation: warps 0..7, two columns per warp ----
    {
        int k   = lane & 15;
        int col = wid + ((lane >> 4) << 3);
        float2 v = make_float2(k == col ? 1.0f : 0.0f, 0.0f);
#pragma unroll
        for (int g = 0; g < 24; ++g) {
            float2 m00 = sm[g][0], m01 = sm[g][1], m10 = sm[g][2], m11 = sm[g][3];
            float px = __shfl_xor_sync(0xffffffffu, v.x, PS.sh[g]);
            float py = __shfl_xor_sync(0xffffffffu, v.y, PS.sh[g]);
            float2 p = make_float2(px, py);
            bool hi = (__popc(k & PS.sel[g]) & 1) != 0;
            float2 cv = hi ? m11 : m00;
            float2 cp = hi ? m10 : m01;
            float2 a = cmul(cv, v), b = cmul(cp, p);
            v = make_float2(a.x + b.x, a.y + b.y);
        }
        sUc[col * 16 + PS.fin[k]] = v;
    }
    __syncthreads();

    // ---- B fragments (main GEMM): W[j][2k+c] = (c? Im:Re) U[k][j], hi/lo ----
    float bhi[2][4][2], blo[2][4][2];
#pragma unroll
    for (int kt = 0; kt < 2; ++kt)
#pragma unroll
    for (int nt = 0; nt < 4; ++nt) {
        int gn   = nt * 8 + gid;       // global output column
        int ko   = gn >> 1;            // k index
        int comp = gn & 1;             // 0=Re, 1=Im
#pragma unroll
        for (int r = 0; r < 2; ++r) {
            int j = tid4 + r * 4 + kt * 8;
            float2 u = sUc[j * 16 + ko];
            float w  = comp ? u.y : u.x;
            float wh = tf32_hi(w);
            bhi[kt][nt][r] = wh;
            blo[kt][nt][r] = w - wh;
        }
    }

    // ---- B fragments (Z-sign reduction mma): Zs[k][q], ±1, q<4; else 0 ----
    float zb[2][2];
#pragma unroll
    for (int kt = 0; kt < 2; ++kt) {
        int k0 = kt * 8 + tid4, k1 = k0 + 4;
        if (gid < 4) {
            zb[kt][0] = 1.0f - 2.0f * (float)((k0 >> (3 - gid)) & 1);
            zb[kt][1] = 1.0f - 2.0f * (float)((k1 >> (3 - gid)) & 1);
        } else {
            zb[kt][0] = 0.0f;
            zb[kt][1] = 0.0f;
        }
    }

    int W = gridDim.x * WARPS;
    int g = blockIdx.x * WARPS + wid;

#pragma unroll 1
    for (; g < NGROUPS; g += W) {
        int base = g * 32;

        // ---- process the two 16-row halves sequentially (register cap) ----
#pragma unroll
        for (int mt = 0; mt < 2; ++mt) {
            // A fragments for elements m = 2mt, 2mt+1 (rows gid+8m):
            // Ahi/Alo[u][t] = split of s_{tid4+4t}(elem) = h[t]*l[tid4]
            float Ahi[2][4], Alo[2][4];
#pragma unroll
            for (int u = 0; u < 2; ++u) {
                float4 xa = x4[base + gid + 8 * (2 * mt + u)];
                float c0, s0, c1, s1, c2, s2, c3, s3;
                __sincosf(0.5f * xa.x, &s0, &c0);
                __sincosf(0.5f * xa.y, &s1, &c1);
                __sincosf(0.5f * xa.z, &s2, &c2);
                __sincosf(0.5f * xa.w, &s3, &c3);
                float h0 = c0 * c1, h1 = c0 * s1, h2 = s0 * c1, h3 = s0 * s1;
                float lv = ((tid4 & 2) ? s2 : c2) * ((tid4 & 1) ? s3 : c3);
                float v0 = h0 * lv, v1 = h1 * lv, v2 = h2 * lv, v3 = h3 * lv;
                float w0 = tf32_hi(v0), w1 = tf32_hi(v1);
                float w2 = tf32_hi(v2), w3 = tf32_hi(v3);
                Ahi[u][0] = w0; Ahi[u][1] = w1; Ahi[u][2] = w2; Ahi[u][3] = w3;
                Alo[u][0] = v0 - w0; Alo[u][1] = v1 - w1;
                Alo[u][2] = v2 - w2; Alo[u][3] = v3 - w3;
            }

            // main GEMM for this half: 24 mma, pass-outer (4 indep C chains)
            float C[4][4];
#pragma unroll
            for (int nt = 0; nt < 4; ++nt)
#pragma unroll
                for (int r = 0; r < 4; ++r) C[nt][r] = 0.0f;

#pragma unroll
            for (int pass = 0; pass < 3; ++pass) {
#pragma unroll
                for (int kt = 0; kt < 2; ++kt) {
                    const float (*Asel)[4] = (pass == 2) ? Alo : Ahi;
                    float a0 = Asel[0][2 * kt];
                    float a1 = Asel[1][2 * kt];
                    float a2 = Asel[0][2 * kt + 1];
                    float a3 = Asel[1][2 * kt + 1];
                    const float (*Bsel)[4][2] = (pass == 1) ? blo : bhi;
#pragma unroll
                    for (int nt = 0; nt < 4; ++nt)
                        mma_tf32(C[nt], a0, a1, a2, a3,
                                 Bsel[kt][nt][0], Bsel[kt][nt][1]);
                }
            }

            // epilogue: p = |t|^2, tensor-core Z-sign reduction (2-pass)
            float p0h[4], p0l[4], p1h[4], p1l[4];
#pragma unroll
            for (int nt = 0; nt < 4; ++nt) {
                float re0 = C[nt][0], im0 = C[nt][1];
                float re1 = C[nt][2], im1 = C[nt][3];
                float p0 = re0 * re0 + im0 * im0;
                float p1 = re1 * re1 + im1 * im1;
                float h0 = tf32_hi(p0), h1 = tf32_hi(p1);
                p0h[nt] = h0; p0l[nt] = p0 - h0;
                p1h[nt] = h1; p1l[nt] = p1 - h1;
            }
            float D[4] = {0.f, 0.f, 0.f, 0.f};
#pragma unroll
            for (int kt = 0; kt < 2; ++kt) {
                mma_tf32(D, p0h[2 * kt], p1h[2 * kt],
                            p0h[2 * kt + 1], p1h[2 * kt + 1],
                            zb[kt][0], zb[kt][1]);
                mma_tf32(D, p0l[2 * kt], p1l[2 * kt],
                            p0l[2 * kt + 1], p1l[2 * kt + 1],
                            zb[kt][0], zb[kt][1]);
            }
            // D: d0/d1 = out[row gid][q=2tid4,2tid4+1]; d2/d3 row gid+8.
            // tid4=0 holds (q0,q1), tid4=1 holds (q2,q3); gather via xor-1.
            float e0 = __shfl_xor_sync(0xffffffffu, D[0], 1);
            float e1 = __shfl_xor_sync(0xffffffffu, D[1], 1);
            float e2 = __shfl_xor_sync(0xffffffffu, D[2], 1);
            float e3 = __shfl_xor_sync(0xffffffffu, D[3], 1);
            if (tid4 == 0) {
                out4[base + mt * 16 + gid]     = make_float4(D[0], D[1], e0, e1);
                out4[base + mt * 16 + gid + 8] = make_float4(D[2], D[3], e2, e3);
            }
        }
    }
}

extern "C" void kernel_launch(void* const* d_in, const int* in_sizes, int n_in,
                              void* d_out, int out_size) {
    const float* x   = (const float*)d_in[0];
    const float* wts = (const float*)d_in[1];
    if (n_in >= 2 && in_sizes[0] == 72 && in_sizes[1] != 72) {
        wts = (const float*)d_in[0];
        x   = (const float*)d_in[1];
    }
    // 3 CTAs per SM (148 SMs): single occ-3 wave; grid-stride covers all.
    int grid = 444;
    qtc_kernel<<<grid, 256>>>((const float4*)x, wts, (float4*)d_out);
}

// round 17
// speedup vs baseline: 1.1191x; 1.1191x over previous
#include <cuda_runtime.h>
#include <cstdint>

// ---------------------------------------------------------------------------
// Compile-time schedule: fold the 24 CNOT permutations (GF(2)-linear) into
// the gate shuffle masks (see R9).
// ---------------------------------------------------------------------------
struct PermSched { int sh[24]; int sel[24]; int fin[16]; };

constexpr PermSched make_sched() {
    PermSched P{};
    int F[4] = {1, 2, 4, 8};
    int G[4] = {1, 2, 4, 8};
    int g = 0;
    for (int l = 0; l < 6; ++l) {
        for (int w = 0; w < 4; ++w) {
            int b = 3 - w;
            P.sh[g] = G[b];
            int S = 0;
            for (int j = 0; j < 4; ++j) S |= ((F[j] >> b) & 1) << j;
            P.sel[g] = S;
            ++g;
        }
        int r = l % 3 + 1;
        for (int w = 0; w < 4; ++w) {
            int bc = 3 - w, bt = 3 - ((w + r) & 3);
            for (int b2 = 0; b2 < 4; ++b2)
                if ((F[b2] >> bc) & 1) F[b2] ^= (1 << bt);
            G[bc] ^= G[bt];
        }
    }
    for (int k = 0; k < 16; ++k) {
        int t = 0;
        for (int b = 0; b < 4; ++b) if ((k >> b) & 1) t ^= F[b];
        P.fin[k] = t;
    }
    return P;
}
__device__ constexpr PermSched PS = make_sched();

__device__ __forceinline__ float2 cmul(float2 a, float2 b) {
    return make_float2(a.x * b.x - a.y * b.y, a.x * b.y + a.y * b.x);
}

// tf32 truncation split (Z-epilogue only)
__device__ __forceinline__ float tf32_hi(float x) {
    return __uint_as_float(__float_as_uint(x) & 0xFFFFE000u);
}
// bf16 truncation residual: v - trunc_bf16(v)  (exact subtraction)
__device__ __forceinline__ float bf16_res(float v) {
    return v - __uint_as_float(__float_as_uint(v) & 0xFFFF0000u);
}
// Pack two floats' top-16 bits into a bf16x2 reg: low half = a, high = b.
// (PRMT does truncate-to-bf16 + pack in ONE instruction.)
__device__ __forceinline__ uint32_t pack_bf16(float a, float b) {
    uint32_t r;
    asm("prmt.b32 %0, %1, %2, 0x7632;"
        : "=r"(r) : "r"(__float_as_uint(a)), "r"(__float_as_uint(b)));
    return r;
}

// m16n8k8 tf32 warp MMA (Z-epilogue), C += A*B
__device__ __forceinline__ void mma_tf32(float* c,
                                         float a0, float a1, float a2, float a3,
                                         float b0, float b1) {
    asm volatile(
        "mma.sync.aligned.m16n8k8.row.col.f32.tf32.tf32.f32 "
        "{%0,%1,%2,%3}, {%4,%5,%6,%7}, {%8,%9}, {%0,%1,%2,%3};"
        : "+f"(c[0]), "+f"(c[1]), "+f"(c[2]), "+f"(c[3])
        : "r"(__float_as_uint(a0)), "r"(__float_as_uint(a1)),
          "r"(__float_as_uint(a2)), "r"(__float_as_uint(a3)),
          "r"(__float_as_uint(b0)), "r"(__float_as_uint(b1)));
}

// m16n8k16 bf16 warp MMA (main GEMM), C += A*B
__device__ __forceinline__ void mma_bf16(float* c,
                                         uint32_t a0, uint32_t a1,
                                         uint32_t a2, uint32_t a3,
                                         uint32_t b0, uint32_t b1) {
    asm volatile(
        "mma.sync.aligned.m16n8k16.row.col.f32.bf16.bf16.f32 "
        "{%0,%1,%2,%3}, {%4,%5,%6,%7}, {%8,%9}, {%0,%1,%2,%3};"
        : "+f"(c[0]), "+f"(c[1]), "+f"(c[2]), "+f"(c[3])
        : "r"(a0), "r"(a1), "r"(a2), "r"(a3), "r"(b0), "r"(b1));
}

#define WARPS 8
#define NGROUPS 8192   // 262144 / 32

// ---------------------------------------------------------------------------
// Fused tensor-core kernel: bf16 m16n8k16 main GEMM (3-pass truncation split,
// 24 mma/group) + tf32 tensor-core Z-sign epilogue (8 mma/group).
// Zero-staging A (s_j = h*l computed per lane), grid-stride balanced, occ 2.
// ---------------------------------------------------------------------------
__global__ __launch_bounds__(256, 2)
void qtc_kernel(const float4* __restrict__ x4, const float* __restrict__ wts,
                float4* __restrict__ out4) {
    __shared__ float2 sUc[256];    // sUc[j*16 + k] = U[k][j]
    __shared__ float2 sm[24][4];

    int tid  = threadIdx.x;
    int wid  = tid >> 5;
    int lane = tid & 31;
    int gid  = lane >> 2;   // mma "groupID"
    int tid4 = lane & 3;    // mma "threadID_in_group"

    // ---- gate matrices ----
    if (tid < 24) {
        float ph = wts[tid * 3 + 0];
        float th = wts[tid * 3 + 1];
        float om = wts[tid * 3 + 2];
        float st, ct; __sincosf(0.5f * th, &st, &ct);
        float sa, ca; __sincosf(0.5f * (ph + om), &sa, &ca);
        float sb, cb; __sincosf(0.5f * (ph - om), &sb, &cb);
        sm[tid][0] = make_float2( ca * ct, -sa * ct);
        sm[tid][1] = make_float2(-cb * st, -sb * st);
        sm[tid][2] = make_float2( cb * st, -sb * st);
        sm[tid][3] = make_float2( ca * ct,  sa * ct);
    }
    __syncthreads();

    // ---- U propagation: warps 0..7, two columns per warp ----
    {
        int k   = lane & 15;
        int col = wid + ((lane >> 4) << 3);
        float2 v = make_float2(k == col ? 1.0f : 0.0f, 0.0f);
#pragma unroll
        for (int g = 0; g < 24; ++g) {
            float2 m00 = sm[g][0], m01 = sm[g][1], m10 = sm[g][2], m11 = sm[g][3];
            float px = __shfl_xor_sync(0xffffffffu, v.x, PS.sh[g]);
            float py = __shfl_xor_sync(0xffffffffu, v.y, PS.sh[g]);
            float2 p = make_float2(px, py);
            bool hi = (__popc(k & PS.sel[g]) & 1) != 0;
            float2 cv = hi ? m11 : m00;
            float2 cp = hi ? m10 : m01;
            float2 a = cmul(cv, v), b = cmul(cp, p);
            v = make_float2(a.x + b.x, a.y + b.y);
        }
        sUc[col * 16 + PS.fin[k]] = v;
    }
    __syncthreads();

    // ---- B fragments (bf16 main GEMM): W[j][n] = (n&1? Im:Re) U[n>>1][j]
    //      b0 = {W[2tid4][gn], W[2tid4+1][gn]}, b1 = rows +8,+9 ----
    uint32_t bhi[4][2], blo[4][2];
#pragma unroll
    for (int nt = 0; nt < 4; ++nt) {
        int gn   = nt * 8 + gid;
        int ko   = gn >> 1;
        int comp = gn & 1;
        float2 u0 = sUc[(2 * tid4 + 0) * 16 + ko];
        float2 u1 = sUc[(2 * tid4 + 1) * 16 + ko];
        float2 u2 = sUc[(2 * tid4 + 8) * 16 + ko];
        float2 u3 = sUc[(2 * tid4 + 9) * 16 + ko];
        float w0 = comp ? u0.y : u0.x;
        float w1 = comp ? u1.y : u1.x;
        float w2 = comp ? u2.y : u2.x;
        float w3 = comp ? u3.y : u3.x;
        bhi[nt][0] = pack_bf16(w0, w1);
        bhi[nt][1] = pack_bf16(w2, w3);
        blo[nt][0] = pack_bf16(bf16_res(w0), bf16_res(w1));
        blo[nt][1] = pack_bf16(bf16_res(w2), bf16_res(w3));
    }

    // ---- B fragments (tf32 Z-sign mma): Zs[k][q], ±1 for q<4, else 0 ----
    float zb[2][2];
#pragma unroll
    for (int kt = 0; kt < 2; ++kt) {
        int k0 = kt * 8 + tid4, k1 = k0 + 4;
        if (gid < 4) {
            zb[kt][0] = 1.0f - 2.0f * (float)((k0 >> (3 - gid)) & 1);
            zb[kt][1] = 1.0f - 2.0f * (float)((k1 >> (3 - gid)) & 1);
        } else {
            zb[kt][0] = 0.0f;
            zb[kt][1] = 0.0f;
        }
    }

    int W = gridDim.x * WARPS;
    int g = blockIdx.x * WARPS + wid;

    float4 xv[4];
    if (g < NGROUPS) {
#pragma unroll
        for (int i = 0; i < 4; ++i) xv[i] = x4[g * 32 + gid + 8 * i];
    }

#pragma unroll 1
    for (; g < NGROUPS; g += W) {
        int base = g * 32;

        // ---- A fragments (bf16, packed): element(i) = base + gid + 8i,
        //      mt = i>>1, u = i&1 (row gid + 8u of the mt half).
        //      Lane needs s_j for j = 2tid4, 2tid4+1, 2tid4+8, 2tid4+9:
        //      s_j = h[j>>2] * l[j&3] ->
        //      f1 = (tid4&2)? s1:c1; hlo = c0*f1, hhi = s0*f1;
        //      f2 = (tid4&1)? s2:c2; la = f2*c3, lb = f2*s3.
        uint32_t Ahi[2][4], Alo[2][4];
#pragma unroll
        for (int i = 0; i < 4; ++i) {
            float4 xa = xv[i];
            float c0, s0, c1, s1, c2, s2, c3, s3;
            __sincosf(0.5f * xa.x, &s0, &c0);
            __sincosf(0.5f * xa.y, &s1, &c1);
            __sincosf(0.5f * xa.z, &s2, &c2);
            __sincosf(0.5f * xa.w, &s3, &c3);
            float f1  = (tid4 & 2) ? s1 : c1;
            float hlo = c0 * f1, hhi = s0 * f1;
            float f2  = (tid4 & 1) ? s2 : c2;
            float la  = f2 * c3, lb = f2 * s3;
            float v0 = hlo * la, v1 = hlo * lb;   // j = 2tid4, 2tid4+1
            float v2 = hhi * la, v3 = hhi * lb;   // j = 2tid4+8, 2tid4+9
            int mt = i >> 1, u = i & 1;
            Ahi[mt][u]     = pack_bf16(v0, v1);
            Ahi[mt][u + 2] = pack_bf16(v2, v3);
            Alo[mt][u]     = pack_bf16(bf16_res(v0), bf16_res(v1));
            Alo[mt][u + 2] = pack_bf16(bf16_res(v2), bf16_res(v3));
        }

        // ---- prefetch next group's x ----
        int gn2 = g + W;
        if (gn2 < NGROUPS) {
#pragma unroll
            for (int i = 0; i < 4; ++i) xv[i] = x4[gn2 * 32 + gid + 8 * i];
        }

        // ---- main GEMM: 24 bf16 mma, pass-outer (8 indep C chains) ----
        float C[2][4][4];
#pragma unroll
        for (int mt = 0; mt < 2; ++mt)
#pragma unroll
            for (int nt = 0; nt < 4; ++nt)
#pragma unroll
                for (int r = 0; r < 4; ++r) C[mt][nt][r] = 0.0f;

#pragma unroll
        for (int pass = 0; pass < 3; ++pass) {
#pragma unroll
            for (int mt = 0; mt < 2; ++mt) {
                const uint32_t* A = (pass == 2) ? Alo[mt] : Ahi[mt];
                const uint32_t (*B)[2] = (pass == 1) ? blo : bhi;
#pragma unroll
                for (int nt = 0; nt < 4; ++nt)
                    mma_bf16(C[mt][nt], A[0], A[1], A[2], A[3],
                             B[nt][0], B[nt][1]);
            }
        }

        // ---- epilogue: p = |t|^2, tf32 tensor-core Z-sign reduction ----
#pragma unroll
        for (int mt = 0; mt < 2; ++mt) {
            float p0h[4], p0l[4], p1h[4], p1l[4];
#pragma unroll
            for (int nt = 0; nt < 4; ++nt) {
                float re0 = C[mt][nt][0], im0 = C[mt][nt][1];
                float re1 = C[mt][nt][2], im1 = C[mt][nt][3];
                float p0 = re0 * re0 + im0 * im0;
                float p1 = re1 * re1 + im1 * im1;
                float h0 = tf32_hi(p0), h1 = tf32_hi(p1);
                p0h[nt] = h0; p0l[nt] = p0 - h0;
                p1h[nt] = h1; p1l[nt] = p1 - h1;
            }
            float D[4] = {0.f, 0.f, 0.f, 0.f};
#pragma unroll
            for (int kt = 0; kt < 2; ++kt) {
                mma_tf32(D, p0h[2 * kt], p1h[2 * kt],
                            p0h[2 * kt + 1], p1h[2 * kt + 1],
                            zb[kt][0], zb[kt][1]);
                mma_tf32(D, p0l[2 * kt], p1l[2 * kt],
                            p0l[2 * kt + 1], p1l[2 * kt + 1],
                            zb[kt][0], zb[kt][1]);
            }
            // D: d0/d1 = out[row gid][q=2tid4, 2tid4+1]; d2/d3 row gid+8.
            // tid4=0 holds (q0,q1), tid4=1 holds (q2,q3); gather via xor-1.
            float e0 = __shfl_xor_sync(0xffffffffu, D[0], 1);
            float e1 = __shfl_xor_sync(0xffffffffu, D[1], 1);
            float e2 = __shfl_xor_sync(0xffffffffu, D[2], 1);
            float e3 = __shfl_xor_sync(0xffffffffu, D[3], 1);
            if (tid4 == 0) {
                out4[base + mt * 16 + gid]     = make_float4(D[0], D[1], e0, e1);
                out4[base + mt * 16 + gid + 8] = make_float4(D[2], D[3], e2, e3);
            }
        }
    }
}

extern "C" void kernel_launch(void* const* d_in, const int* in_sizes, int n_in,
                              void* d_out, int out_size) {
    const float* x   = (const float*)d_in[0];
    const float* wts = (const float*)d_in[1];
    if (n_in >= 2 && in_sizes[0] == 72 && in_sizes[1] != 72) {
        wts = (const float*)d_in[0];
        x   = (const float*)d_in[1];
    }
    // 2 CTAs per SM (148 SMs): exact wave balance; grid-stride covers all.
    int grid = 296;
    qtc_kernel<<<grid, 256>>>((const float4*)x, wts, (float4*)d_out);
}